// round 1
// baseline (speedup 1.0000x reference)
#include <cuda_runtime.h>
#include <math.h>

// Problem constants
#define Bz   16
#define LC   512
#define LQ   64
#define Hd   256
#define Dd   1024      // 4*H
#define DFF  512
#define Cc   3
#define D1   1025      // D+1
#define LD1  1028      // padded row stride for s1/e1/T (16B aligned)
#define ROWS (Bz*LC)   // 8192

// -------------------- device scratch (zero-initialized) --------------------
__device__ float g_q2[Bz*LQ];
__device__ float g_rowmax[ROWS];
__device__ float g_q2c[Bz*Hd];
__device__ float g_x[(long long)ROWS*Dd];        // [8192,1024]
__device__ float g_h1[(long long)ROWS*DFF];      // [8192,512]
__device__ float g_s1[(long long)ROWS*LD1];      // [8192,1028] col1024=1, pads 0
__device__ float g_e1[(long long)ROWS*LD1];
__device__ float g_T[(long long)Bz*Cc*LC*LD1];   // [48,512,1028]

// -------------------- small kernels --------------------

// q2[b,j] = dot(ques[b,j,:], w2)
__global__ void qdot_kernel(const float* __restrict__ ques, const float* __restrict__ wsim,
                            float* __restrict__ q2) {
    int b = blockIdx.x, j = blockIdx.y, l = threadIdx.x;
    const float* q = ques + ((long long)(b*LQ + j))*Hd;
    float s = 0.f;
    #pragma unroll
    for (int u = 0; u < Hd/32; u++) s += q[l + u*32] * wsim[Hd + l + u*32];
    #pragma unroll
    for (int o = 16; o > 0; o >>= 1) s += __shfl_down_sync(0xffffffffu, s, o);
    if (l == 0) q2[b*LQ + j] = s;
}

// per (b,i): sim row, softmax over j, c2q, rowmax; writes x[:,0:768]
__global__ void sim_softmax_c2q_kernel(const float* __restrict__ ctx,
                                       const float* __restrict__ ques,
                                       const float* __restrict__ wsim,
                                       const float* __restrict__ q2,
                                       float* __restrict__ x,
                                       float* __restrict__ rowmax) {
    int row = blockIdx.x;            // b*512 + i
    int b = row >> 9;
    int t = threadIdx.x;             // 256
    int w = t >> 5, l = t & 31;

    __shared__ float ctxs[Hd], cw3[Hd], simv[LQ], sred[8];
    __shared__ float c1s;

    const float* crow = ctx + (long long)row * Hd;
    float cv = crow[t];
    ctxs[t] = cv;
    cw3[t]  = cv * wsim[2*Hd + t];

    // c1 = dot(ctx, w1)
    float v = cv * wsim[t];
    #pragma unroll
    for (int o = 16; o > 0; o >>= 1) v += __shfl_down_sync(0xffffffffu, v, o);
    if (l == 0) sred[w] = v;
    __syncthreads();
    if (t == 0) {
        float s = 0.f;
        #pragma unroll
        for (int u = 0; u < 8; u++) s += sred[u];
        c1s = s;
    }
    __syncthreads();

    // sim[j] = c1 + q2[b,j] + dot(cw3, ques[b,j,:])   (warp w handles 8 j's)
    const float* qb = ques + (long long)b * LQ * Hd;
    #pragma unroll
    for (int jj = 0; jj < 8; jj++) {
        int j = w * 8 + jj;
        const float* q = qb + (long long)j * Hd;
        float s = 0.f;
        #pragma unroll
        for (int u = 0; u < Hd/32; u++) s += cw3[l + u*32] * q[l + u*32];
        #pragma unroll
        for (int o = 16; o > 0; o >>= 1) s += __shfl_down_sync(0xffffffffu, s, o);
        if (l == 0) simv[j] = c1s + q2[b*LQ + j] + s;
    }
    __syncthreads();

    // softmax over the 64 sims (warp 0), record rowmax (pre-softmax max)
    if (t < 32) {
        float s0 = simv[t], s1v = simv[t + 32];
        float m = fmaxf(s0, s1v);
        #pragma unroll
        for (int o = 16; o > 0; o >>= 1) m = fmaxf(m, __shfl_xor_sync(0xffffffffu, m, o));
        if (t == 0) rowmax[row] = m;
        float e0 = expf(s0 - m), e1v = expf(s1v - m);
        float sum = e0 + e1v;
        #pragma unroll
        for (int o = 16; o > 0; o >>= 1) sum += __shfl_xor_sync(0xffffffffu, sum, o);
        float inv = 1.f / sum;
        simv[t] = e0 * inv; simv[t + 32] = e1v * inv;
    }
    __syncthreads();

    // c2q[h] = sum_j a_j * ques[b,j,h]; write x[row, 0:768]
    float acc = 0.f;
    #pragma unroll 8
    for (int j = 0; j < LQ; j++) acc += simv[j] * qb[(long long)j*Hd + t];

    float* xr = x + (long long)row * Dd;
    xr[t]        = ctxs[t];
    xr[Hd + t]   = acc;
    xr[2*Hd + t] = ctxs[t] * acc;
}

// per batch: softmax over rowmax[b,:] (axis i), then q2c[b,h]
__global__ void bsoftmax_q2c_kernel(const float* __restrict__ ctx,
                                    const float* __restrict__ rowmax,
                                    float* __restrict__ q2c) {
    int b = blockIdx.x, t = threadIdx.x;   // 256 threads
    __shared__ float w[LC];
    __shared__ float sred[8];
    __shared__ float mshared, sshared;

    w[t] = rowmax[b*LC + t];
    w[t + 256] = rowmax[b*LC + t + 256];
    __syncthreads();

    float m = fmaxf(w[t], w[t + 256]);
    #pragma unroll
    for (int o = 16; o > 0; o >>= 1) m = fmaxf(m, __shfl_xor_sync(0xffffffffu, m, o));
    if ((t & 31) == 0) sred[t >> 5] = m;
    __syncthreads();
    if (t == 0) {
        float mm = sred[0];
        #pragma unroll
        for (int u = 1; u < 8; u++) mm = fmaxf(mm, sred[u]);
        mshared = mm;
    }
    __syncthreads();
    m = mshared;

    float e0 = expf(w[t] - m), e1v = expf(w[t + 256] - m);
    float s = e0 + e1v;
    #pragma unroll
    for (int o = 16; o > 0; o >>= 1) s += __shfl_xor_sync(0xffffffffu, s, o);
    if ((t & 31) == 0) sred[t >> 5] = s;
    __syncthreads();
    if (t == 0) {
        float ss = 0.f;
        #pragma unroll
        for (int u = 0; u < 8; u++) ss += sred[u];
        sshared = ss;
    }
    __syncthreads();
    float inv = 1.f / sshared;
    w[t] = e0 * inv; w[t + 256] = e1v * inv;
    __syncthreads();

    float acc = 0.f;
    const float* cb = ctx + (long long)b * LC * Hd;
    for (int i = 0; i < LC; i++) acc += w[i] * cb[(long long)i*Hd + t];
    q2c[b*Hd + t] = acc;
}

// x[row, 768+h] = ctx[row,h] * q2c[b,h]
__global__ void fillx4_kernel(const float* __restrict__ ctx,
                              const float* __restrict__ q2c,
                              float* __restrict__ x) {
    int row = blockIdx.x, t = threadIdx.x;
    int b = row >> 9;
    float c = ctx[(long long)row*Hd + t];
    x[(long long)row*Dd + 3*Hd + t] = c * q2c[b*Hd + t];
}

// s1/e1: col 1024 = 1, cols 1025..1027 = 0
__global__ void fill_ones_kernel(float* __restrict__ s1, float* __restrict__ e1) {
    int r = blockIdx.x * blockDim.x + threadIdx.x;
    if (r >= ROWS) return;
    long long o = (long long)r * LD1;
    s1[o + 1024] = 1.f; s1[o + 1025] = 0.f; s1[o + 1026] = 0.f; s1[o + 1027] = 0.f;
    e1[o + 1024] = 1.f; e1[o + 1025] = 0.f; e1[o + 1026] = 0.f; e1[o + 1027] = 0.f;
}

// -------------------- generic batched GEMM --------------------
// C = op(A @ opB(B)) with optional bias (per column) and relu.
// Per-z offsets: off = (z/3)*P + (z%3)*Q  for each of A,B,C.
// Tiles: BM=BN=128, BK=8, 256 threads, 8x8 per-thread micro-tile.
#define GBM 128
#define GBN 128
#define GBK 8
#define GPAD 4

__global__ __launch_bounds__(256, 2)
void gemm_kernel(const float* __restrict__ A, const float* __restrict__ Bm,
                 float* __restrict__ C, const float* __restrict__ bias,
                 int M, int N, int K, int lda, int ldb, int ldc, int cColStride,
                 long long aP, long long aQ, long long bP, long long bQ,
                 long long cP, long long cQ, int transB, int relu) {
    __shared__ float As[GBK][GBM + GPAD];
    __shared__ float Bs[GBK][GBN + GPAD];

    int z = blockIdx.z;
    int zb = z / 3, zc = z - zb * 3;
    A  += zb * aP + zc * aQ;
    Bm += zb * bP + zc * bQ;
    C  += zb * cP + zc * cQ;

    int row0 = blockIdx.y * GBM, col0 = blockIdx.x * GBN;
    int tid = threadIdx.x;
    int tx = tid & 15, ty = tid >> 4;

    float acc[8][8];
    #pragma unroll
    for (int i = 0; i < 8; i++)
        #pragma unroll
        for (int j = 0; j < 8; j++) acc[i][j] = 0.f;

    for (int k0 = 0; k0 < K; k0 += GBK) {
        // load A tile: As[k][m]
        #pragma unroll
        for (int t = 0; t < 4; t++) {
            int idx = tid + t * 256;
            int m = idx >> 3, k = idx & 7;
            int gm = row0 + m, gk = k0 + k;
            As[k][m] = (gm < M && gk < K) ? A[(long long)gm * lda + gk] : 0.f;
        }
        // load B tile: Bs[k][n]
        if (!transB) {
            #pragma unroll
            for (int t = 0; t < 4; t++) {
                int idx = tid + t * 256;
                int k = idx >> 7, n = idx & 127;
                int gk = k0 + k, gn = col0 + n;
                Bs[k][n] = (gk < K && gn < N) ? Bm[(long long)gk * ldb + gn] : 0.f;
            }
        } else {
            #pragma unroll
            for (int t = 0; t < 4; t++) {
                int idx = tid + t * 256;
                int n = idx >> 3, k = idx & 7;
                int gk = k0 + k, gn = col0 + n;
                Bs[k][n] = (gk < K && gn < N) ? Bm[(long long)gn * ldb + gk] : 0.f;
            }
        }
        __syncthreads();

        #pragma unroll
        for (int k = 0; k < GBK; k++) {
            float a[8], bv[8];
            const float4* Ap = reinterpret_cast<const float4*>(&As[k][ty * 8]);
            const float4* Bp = reinterpret_cast<const float4*>(&Bs[k][tx * 8]);
            float4 a0 = Ap[0], a1 = Ap[1];
            float4 b0 = Bp[0], b1 = Bp[1];
            a[0]=a0.x; a[1]=a0.y; a[2]=a0.z; a[3]=a0.w;
            a[4]=a1.x; a[5]=a1.y; a[6]=a1.z; a[7]=a1.w;
            bv[0]=b0.x; bv[1]=b0.y; bv[2]=b0.z; bv[3]=b0.w;
            bv[4]=b1.x; bv[5]=b1.y; bv[6]=b1.z; bv[7]=b1.w;
            #pragma unroll
            for (int i = 0; i < 8; i++)
                #pragma unroll
                for (int j = 0; j < 8; j++) acc[i][j] += a[i] * bv[j];
        }
        __syncthreads();
    }

    #pragma unroll
    for (int i = 0; i < 8; i++) {
        int gm = row0 + ty * 8 + i;
        if (gm >= M) continue;
        #pragma unroll
        for (int j = 0; j < 8; j++) {
            int gn = col0 + tx * 8 + j;
            if (gn >= N) continue;
            float v = acc[i][j];
            if (bias) v += bias[gn];
            if (relu) v = fmaxf(v, 0.f);
            C[(long long)gm * ldc + (long long)gn * cColStride] = v;
        }
    }
}

// -------------------- launcher --------------------
static inline dim3 ggrid(int M, int N, int Z) {
    return dim3((N + GBN - 1) / GBN, (M + GBM - 1) / GBM, Z);
}

extern "C" void kernel_launch(void* const* d_in, const int* in_sizes, int n_in,
                              void* d_out, int out_size) {
    const float* ctx  = (const float*)d_in[0];
    const float* ques = (const float*)d_in[1];
    const float* wsim = (const float*)d_in[2];
    const float* W1s  = (const float*)d_in[3];
    const float* b1s  = (const float*)d_in[4];
    const float* W2s  = (const float*)d_in[5];
    const float* b2s  = (const float*)d_in[6];
    const float* W1e  = (const float*)d_in[7];
    const float* b1e  = (const float*)d_in[8];
    const float* W2e  = (const float*)d_in[9];
    const float* b2e  = (const float*)d_in[10];
    const float* Wb   = (const float*)d_in[11];
    float* out = (float*)d_out;

    float *q2, *rowmax, *q2c, *x, *h1, *s1, *e1, *T;
    cudaGetSymbolAddress((void**)&q2, g_q2);
    cudaGetSymbolAddress((void**)&rowmax, g_rowmax);
    cudaGetSymbolAddress((void**)&q2c, g_q2c);
    cudaGetSymbolAddress((void**)&x, g_x);
    cudaGetSymbolAddress((void**)&h1, g_h1);
    cudaGetSymbolAddress((void**)&s1, g_s1);
    cudaGetSymbolAddress((void**)&e1, g_e1);
    cudaGetSymbolAddress((void**)&T, g_T);

    // attention front-end
    qdot_kernel<<<dim3(Bz, LQ), 32>>>(ques, wsim, q2);
    sim_softmax_c2q_kernel<<<ROWS, 256>>>(ctx, ques, wsim, q2, x, rowmax);
    bsoftmax_q2c_kernel<<<Bz, 256>>>(ctx, rowmax, q2c);
    fillx4_kernel<<<ROWS, 256>>>(ctx, q2c, x);
    fill_ones_kernel<<<(ROWS + 255) / 256, 256>>>(s1, e1);

    // FFW start: h1 = relu(x@W1s + b1s); s1[:, :1024] = h1@W2s + b2s
    gemm_kernel<<<ggrid(ROWS, DFF, 1), 256>>>(x, W1s, h1, b1s,
        ROWS, DFF, Dd, Dd, DFF, DFF, 1, 0,0, 0,0, 0,0, 0, 1);
    gemm_kernel<<<ggrid(ROWS, Dd, 1), 256>>>(h1, W2s, s1, b2s,
        ROWS, Dd, DFF, DFF, Dd, LD1, 1, 0,0, 0,0, 0,0, 0, 0);
    // FFW end
    gemm_kernel<<<ggrid(ROWS, DFF, 1), 256>>>(x, W1e, h1, b1e,
        ROWS, DFF, Dd, Dd, DFF, DFF, 1, 0,0, 0,0, 0,0, 0, 1);
    gemm_kernel<<<ggrid(ROWS, Dd, 1), 256>>>(h1, W2e, e1, b2e,
        ROWS, Dd, DFF, DFF, Dd, LD1, 1, 0,0, 0,0, 0,0, 0, 0);

    // Biaffine stage 1: T[b,c] = s1_b @ Wb[:,c,:]   (z = b*3+c)
    // A = s1 + (z/3)*LC*LD1 ; B = Wb + (z%3)*D1 (ldb = 3*D1) ; C = T + z*LC*LD1
    gemm_kernel<<<ggrid(LC, D1, Bz * Cc), 256>>>(s1, Wb, T, nullptr,
        LC, D1, D1, LD1, Cc * D1, LD1, 1,
        (long long)LC * LD1, 0,            // A: per-b
        0, (long long)D1,                  // B: per-c
        (long long)Cc * LC * LD1, (long long)LC * LD1,  // C: z*LC*LD1
        0, 0);

    // Biaffine stage 2: out[b,x,y,c] = T[b,c] @ e1_b^T  (transB)
    // C offset = b*LC*LC*3 + c, ldc = LC*3, col stride 3
    gemm_kernel<<<ggrid(LC, LC, Bz * Cc), 256>>>(T, e1, out, nullptr,
        LC, LC, D1, LD1, LD1, LC * Cc, Cc,
        (long long)Cc * LC * LD1, (long long)LC * LD1,  // A = T[z]
        (long long)LC * LD1, 0,                          // B = e1_b
        (long long)LC * LC * Cc, 1,                      // C
        1, 0);
}

// round 3
// speedup vs baseline: 2.1178x; 2.1178x over previous
#include <cuda_runtime.h>
#include <cuda_bf16.h>
#include <cstdint>
#include <math.h>

// Problem constants
#define Bz   16
#define LC   512
#define LQ   64
#define Hd   256
#define ROWS (Bz*LC)     // 8192

// Split-K padded strides (K'' = 3 * Kpad), all in bf16 elements
#define KX   3072        // x'' / W1''  (Kpad=1024)
#define KH   1536        // h1'' / W2'' (Kpad=512)
#define KS   3264        // s1''/e1''/T''/Wbt (Kpad=1088, Kreal=1025)
#define KPAD_S 1088
#define NB1  1152        // wbt padded N rows (9*128)

// -------------------- device scratch (zero-init .bss; pads never written) ---
__device__ float g_q2[Bz*LQ];
__device__ float g_rowmax[ROWS];
__device__ float g_q2c[Bz*Hd];
__device__ __align__(16) __nv_bfloat16 g_xs [(size_t)ROWS*KX];
__device__ __align__(16) __nv_bfloat16 g_h1s[(size_t)ROWS*KH];
__device__ __align__(16) __nv_bfloat16 g_s1s[(size_t)ROWS*KS];
__device__ __align__(16) __nv_bfloat16 g_e1s[(size_t)ROWS*KS];
__device__ __align__(16) __nv_bfloat16 g_Ts [(size_t)48*LC*KS];
__device__ __align__(16) __nv_bfloat16 g_w1s[(size_t)512*KX];
__device__ __align__(16) __nv_bfloat16 g_w1e[(size_t)512*KX];
__device__ __align__(16) __nv_bfloat16 g_w2s[(size_t)1024*KH];
__device__ __align__(16) __nv_bfloat16 g_w2e[(size_t)1024*KH];
__device__ __align__(16) __nv_bfloat16 g_wbt[(size_t)3*NB1*KS];

// -------------------- helpers --------------------
__device__ __forceinline__ uint32_t smem_u32(const void* p) {
    uint32_t a;
    asm("{ .reg .u64 t; cvta.to.shared.u64 t, %1; cvt.u32.u64 %0, t; }" : "=r"(a) : "l"(p));
    return a;
}
__device__ __forceinline__ void cp16(uint32_t saddr, const void* g) {
    asm volatile("cp.async.ca.shared.global [%0], [%1], 16;" :: "r"(saddr), "l"(g) : "memory");
}
__device__ __forceinline__ void cp_commit() { asm volatile("cp.async.commit_group;" ::: "memory"); }
__device__ __forceinline__ void cp_wait0()  { asm volatile("cp.async.wait_group 0;" ::: "memory"); }

__device__ __forceinline__ void split2(float v, __nv_bfloat16& hi, __nv_bfloat16& lo) {
    hi = __float2bfloat16(v);
    lo = __float2bfloat16(v - __bfloat162float(hi));
}
__device__ __forceinline__ unsigned short b16bits(__nv_bfloat16 h) {
    return *reinterpret_cast<unsigned short*>(&h);
}

// -------------------- attention front-end --------------------
__device__ __forceinline__ void xsplit_store(__nv_bfloat16* xr, int col, float v) {
    __nv_bfloat16 hi, lo; split2(v, hi, lo);
    xr[col] = hi; xr[col + 1024] = lo; xr[col + 2048] = hi;   // A-layout: hi, lo, hi
}

__global__ void qdot_kernel(const float* __restrict__ ques, const float* __restrict__ wsim,
                            float* __restrict__ q2) {
    int b = blockIdx.x, j = blockIdx.y, l = threadIdx.x;
    const float* q = ques + ((size_t)(b*LQ + j))*Hd;
    float s = 0.f;
    #pragma unroll
    for (int u = 0; u < Hd/32; u++) s += q[l + u*32] * wsim[Hd + l + u*32];
    #pragma unroll
    for (int o = 16; o > 0; o >>= 1) s += __shfl_down_sync(0xffffffffu, s, o);
    if (l == 0) q2[b*LQ + j] = s;
}

__global__ void sim_softmax_c2q_kernel(const float* __restrict__ ctx,
                                       const float* __restrict__ ques,
                                       const float* __restrict__ wsim,
                                       const float* __restrict__ q2,
                                       __nv_bfloat16* __restrict__ xs,
                                       float* __restrict__ rowmax) {
    int row = blockIdx.x, b = row >> 9;
    int t = threadIdx.x, w = t >> 5, l = t & 31;
    __shared__ float ctxs[Hd], cw3[Hd], simv[LQ], sred[8];
    __shared__ float c1s;

    const float* crow = ctx + (size_t)row * Hd;
    float cv = crow[t];
    ctxs[t] = cv;
    cw3[t]  = cv * wsim[2*Hd + t];

    float v = cv * wsim[t];
    #pragma unroll
    for (int o = 16; o > 0; o >>= 1) v += __shfl_down_sync(0xffffffffu, v, o);
    if (l == 0) sred[w] = v;
    __syncthreads();
    if (t == 0) { float s = 0.f; for (int u = 0; u < 8; u++) s += sred[u]; c1s = s; }
    __syncthreads();

    const float* qb = ques + (size_t)b * LQ * Hd;
    #pragma unroll
    for (int jj = 0; jj < 8; jj++) {
        int j = w * 8 + jj;
        const float* q = qb + (size_t)j * Hd;
        float s = 0.f;
        #pragma unroll
        for (int u = 0; u < Hd/32; u++) s += cw3[l + u*32] * q[l + u*32];
        #pragma unroll
        for (int o = 16; o > 0; o >>= 1) s += __shfl_down_sync(0xffffffffu, s, o);
        if (l == 0) simv[j] = c1s + q2[b*LQ + j] + s;
    }
    __syncthreads();

    if (t < 32) {
        float s0 = simv[t], s1v = simv[t + 32];
        float m = fmaxf(s0, s1v);
        #pragma unroll
        for (int o = 16; o > 0; o >>= 1) m = fmaxf(m, __shfl_xor_sync(0xffffffffu, m, o));
        if (t == 0) rowmax[row] = m;
        float e0 = expf(s0 - m), e1v = expf(s1v - m);
        float sum = e0 + e1v;
        #pragma unroll
        for (int o = 16; o > 0; o >>= 1) sum += __shfl_xor_sync(0xffffffffu, sum, o);
        float inv = 1.f / sum;
        simv[t] = e0 * inv; simv[t + 32] = e1v * inv;
    }
    __syncthreads();

    float acc = 0.f;
    #pragma unroll 8
    for (int j = 0; j < LQ; j++) acc += simv[j] * qb[(size_t)j*Hd + t];

    __nv_bfloat16* xr = xs + (size_t)row * KX;
    xsplit_store(xr, t,        ctxs[t]);
    xsplit_store(xr, Hd + t,   acc);
    xsplit_store(xr, 2*Hd + t, ctxs[t] * acc);
}

__global__ void bsoftmax_q2c_kernel(const float* __restrict__ ctx,
                                    const float* __restrict__ rowmax,
                                    float* __restrict__ q2c) {
    int b = blockIdx.x, t = threadIdx.x;
    __shared__ float w[LC]; __shared__ float sred[8]; __shared__ float mshared, sshared;
    w[t] = rowmax[b*LC + t]; w[t + 256] = rowmax[b*LC + t + 256];
    __syncthreads();
    float m = fmaxf(w[t], w[t + 256]);
    #pragma unroll
    for (int o = 16; o > 0; o >>= 1) m = fmaxf(m, __shfl_xor_sync(0xffffffffu, m, o));
    if ((t & 31) == 0) sred[t >> 5] = m;
    __syncthreads();
    if (t == 0) { float mm = sred[0]; for (int u = 1; u < 8; u++) mm = fmaxf(mm, sred[u]); mshared = mm; }
    __syncthreads();
    m = mshared;
    float e0 = expf(w[t] - m), e1v = expf(w[t + 256] - m);
    float s = e0 + e1v;
    #pragma unroll
    for (int o = 16; o > 0; o >>= 1) s += __shfl_xor_sync(0xffffffffu, s, o);
    if ((t & 31) == 0) sred[t >> 5] = s;
    __syncthreads();
    if (t == 0) { float ss = 0.f; for (int u = 0; u < 8; u++) ss += sred[u]; sshared = ss; }
    __syncthreads();
    float inv = 1.f / sshared;
    w[t] = e0 * inv; w[t + 256] = e1v * inv;
    __syncthreads();
    float acc = 0.f;
    const float* cb = ctx + (size_t)b * LC * Hd;
    for (int i = 0; i < LC; i++) acc += w[i] * cb[(size_t)i*Hd + t];
    q2c[b*Hd + t] = acc;
}

__global__ void fillx4_kernel(const float* __restrict__ ctx,
                              const float* __restrict__ q2c,
                              __nv_bfloat16* __restrict__ xs) {
    int row = blockIdx.x, t = threadIdx.x, b = row >> 9;
    float c = ctx[(size_t)row*Hd + t];
    xsplit_store(xs + (size_t)row*KX, 3*Hd + t, c * q2c[b*Hd + t]);
}

// s1''/e1'' constant columns 1024..1087 for all three K-blocks
__global__ void fill_const_kernel(__nv_bfloat16* __restrict__ s1, __nv_bfloat16* __restrict__ e1) {
    int r = blockIdx.x, t = threadIdx.x;       // t in [0,64)
    int k = 1024 + t;
    __nv_bfloat16 v = __float2bfloat16(t == 0 ? 1.f : 0.f);
    __nv_bfloat16 z = __float2bfloat16(0.f);
    size_t base = (size_t)r * KS + k;
    s1[base] = v; s1[base + KPAD_S] = z; s1[base + 2*KPAD_S] = v;  // hi, lo, hi
    e1[base] = v; e1[base + KPAD_S] = v; e1[base + 2*KPAD_S] = z;  // hi, hi, lo
}

// Transpose + split weights into B-layout [N rows x 3*Kpad]: blocks (hi, hi, lo)
__global__ void prep_bsplit(const float* __restrict__ src, int srcLd,
                            __nv_bfloat16* __restrict__ dst,
                            int Kreal, int Kpad, int Nrows) {
    __shared__ float tile[32][33];
    int k0 = blockIdx.y*32, n0 = blockIdx.x*32;
    int tx = threadIdx.x, ty = threadIdx.y;
    #pragma unroll
    for (int i = 0; i < 32; i += 8) {
        int k = k0 + ty + i, n = n0 + tx;
        tile[ty + i][tx] = (k < Kreal && n < Nrows) ? src[(size_t)k*srcLd + n] : 0.f;
    }
    __syncthreads();
    int ldd = 3*Kpad;
    #pragma unroll
    for (int i = 0; i < 32; i += 8) {
        int n = n0 + ty + i, k = k0 + tx;
        if (n < Nrows) {
            __nv_bfloat16 hi, lo; split2(tile[tx][ty + i], hi, lo);
            size_t base = (size_t)n*ldd + k;
            dst[base] = hi; dst[base + Kpad] = hi; dst[base + 2*Kpad] = lo;
        }
    }
}

// -------------------- warp-mma GEMM (bf16, fp32 acc) --------------------
// D = A @ B^T ; A [M,K''] K-major, B [N,K''] K-major, both padded so the
// loader needs no bounds checks. 128x128x32 block tile, 8 warps, 64x32 warp tile.
#define LDR 40   // smem row stride in bf16 (80 bytes -> 20 banks, conflict-free)

__device__ __forceinline__ void mma16816(float* c, const uint32_t* a, const uint32_t* b) {
    asm volatile(
        "mma.sync.aligned.m16n8k16.row.col.f32.bf16.bf16.f32 "
        "{%0,%1,%2,%3}, {%4,%5,%6,%7}, {%8,%9}, {%0,%1,%2,%3};"
        : "+f"(c[0]), "+f"(c[1]), "+f"(c[2]), "+f"(c[3])
        : "r"(a[0]), "r"(a[1]), "r"(a[2]), "r"(a[3]), "r"(b[0]), "r"(b[1]));
}

__device__ __forceinline__ void store_pair_split(
    __nv_bfloat16* p, int n, int Nreal, float v0, float v1,
    int blk1, int blk2, int b1lo, const float* bias, int relu)
{
    if (n >= Nreal) return;
    if (bias) { v0 += bias[n]; if (n + 1 < Nreal) v1 += bias[n + 1]; }
    if (relu) { v0 = fmaxf(v0, 0.f); v1 = fmaxf(v1, 0.f); }
    __nv_bfloat16 h0, l0, h1, l1;
    split2(v0, h0, l0); split2(v1, h1, l1);
    if (n + 1 < Nreal) {
        uint32_t H = (uint32_t)b16bits(h0) | ((uint32_t)b16bits(h1) << 16);
        uint32_t L = (uint32_t)b16bits(l0) | ((uint32_t)b16bits(l1) << 16);
        *reinterpret_cast<uint32_t*>(p + n) = H;
        *reinterpret_cast<uint32_t*>(p + blk1 + n) = b1lo ? L : H;
        *reinterpret_cast<uint32_t*>(p + blk2 + n) = b1lo ? H : L;
    } else {
        p[n] = h0;
        p[blk1 + n] = b1lo ? l0 : h0;
        p[blk2 + n] = b1lo ? h0 : l0;
    }
}

__global__ __launch_bounds__(256, 2)
void mma_gemm(const __nv_bfloat16* __restrict__ A, int lda, long long aZb, long long aZc,
              const __nv_bfloat16* __restrict__ B, int ldb, long long bZb, long long bZc,
              int Nreal, int nch, int zdiv, int mode,
              __nv_bfloat16* outS, int ldo, int blk1, int blk2, int b1lo,
              const float* bias, int relu,
              float* outF, int ldcM, long long cZb, long long cZc)
{
    __shared__ __align__(16) __nv_bfloat16 sA[2][128*LDR];
    __shared__ __align__(16) __nv_bfloat16 sB[2][128*LDR];

    int tid = threadIdx.x;
    int z = blockIdx.z, zb = z / zdiv, zc = z - zb * zdiv;
    const __nv_bfloat16* Ab = A + (size_t)zb*aZb + (size_t)zc*aZc + (size_t)(blockIdx.y*128)*lda;
    const __nv_bfloat16* Bb = B + (size_t)zb*bZb + (size_t)zc*bZc + (size_t)(blockIdx.x*128)*ldb;
    int m0 = blockIdx.y * 128, n0 = blockIdx.x * 128;

    int lane = tid & 31, wid = tid >> 5;
    int wm = (wid & 1) * 64, wn = (wid >> 1) * 32;
    int ar = lane >> 2, ac = (lane & 3) * 2;

    int lrow = tid >> 2, lseg = tid & 3;               // loader: 4 threads/row
    uint32_t sA0 = smem_u32(&sA[0][0]), sB0 = smem_u32(&sB[0][0]);
    uint32_t sA1 = smem_u32(&sA[1][0]), sB1 = smem_u32(&sB[1][0]);

    float acc[4][4][4];
    #pragma unroll
    for (int i = 0; i < 4; i++)
        #pragma unroll
        for (int j = 0; j < 4; j++)
            #pragma unroll
            for (int q = 0; q < 4; q++) acc[i][j][q] = 0.f;

    // prologue: load chunk 0 into buf 0
    {
        const __nv_bfloat16* ga = Ab + (size_t)lrow*lda + lseg*8;
        const __nv_bfloat16* gb = Bb + (size_t)lrow*ldb + lseg*8;
        uint32_t so = lrow*(LDR*2) + lseg*16;
        cp16(sA0 + so, ga);            cp16(sB0 + so, gb);
        cp16(sA0 + so + 64*(LDR*2), ga + (size_t)64*lda);
        cp16(sB0 + so + 64*(LDR*2), gb + (size_t)64*ldb);
        cp_commit();
    }

    for (int c = 0; c < nch; c++) {
        cp_wait0();
        __syncthreads();
        int buf = c & 1;
        if (c + 1 < nch) {
            int k0 = (c + 1) * 32;
            const __nv_bfloat16* ga = Ab + (size_t)lrow*lda + k0 + lseg*8;
            const __nv_bfloat16* gb = Bb + (size_t)lrow*ldb + k0 + lseg*8;
            uint32_t da = (buf ? sA0 : sA1), db = (buf ? sB0 : sB1);
            uint32_t so = lrow*(LDR*2) + lseg*16;
            cp16(da + so, ga);            cp16(db + so, gb);
            cp16(da + so + 64*(LDR*2), ga + (size_t)64*lda);
            cp16(db + so + 64*(LDR*2), gb + (size_t)64*ldb);
            cp_commit();
        }
        const __nv_bfloat16* As = &sA[buf][0];
        const __nv_bfloat16* Bs = &sB[buf][0];
        #pragma unroll
        for (int ks = 0; ks < 2; ks++) {
            int kc = ks * 16;
            uint32_t af[4][4], bf[4][2];
            #pragma unroll
            for (int mt = 0; mt < 4; mt++) {
                int r0 = wm + mt*16 + ar;
                af[mt][0] = *reinterpret_cast<const uint32_t*>(As + r0*LDR + kc + ac);
                af[mt][1] = *reinterpret_cast<const uint32_t*>(As + (r0+8)*LDR + kc + ac);
                af[mt][2] = *reinterpret_cast<const uint32_t*>(As + r0*LDR + kc + ac + 8);
                af[mt][3] = *reinterpret_cast<const uint32_t*>(As + (r0+8)*LDR + kc + ac + 8);
            }
            #pragma unroll
            for (int nt = 0; nt < 4; nt++) {
                int nr = wn + nt*8 + ar;
                bf[nt][0] = *reinterpret_cast<const uint32_t*>(Bs + nr*LDR + kc + ac);
                bf[nt][1] = *reinterpret_cast<const uint32_t*>(Bs + nr*LDR + kc + ac + 8);
            }
            #pragma unroll
            for (int mt = 0; mt < 4; mt++)
                #pragma unroll
                for (int nt = 0; nt < 4; nt++)
                    mma16816(acc[mt][nt], af[mt], bf[nt]);
        }
        __syncthreads();
    }

    // -------- epilogue --------
    if (mode == 0) {
        __nv_bfloat16* base = outS + (size_t)zb*cZb + (size_t)zc*cZc;
        #pragma unroll
        for (int mt = 0; mt < 4; mt++) {
            int m = m0 + wm + mt*16 + ar;
            __nv_bfloat16* p0 = base + (size_t)m*ldo;
            __nv_bfloat16* p1 = p0 + (size_t)8*ldo;
            #pragma unroll
            for (int nt = 0; nt < 4; nt++) {
                int n = n0 + wn + nt*8 + ac;
                store_pair_split(p0, n, Nreal, acc[mt][nt][0], acc[mt][nt][1],
                                 blk1, blk2, b1lo, bias, relu);
                store_pair_split(p1, n, Nreal, acc[mt][nt][2], acc[mt][nt][3],
                                 blk1, blk2, b1lo, bias, relu);
            }
        }
    } else {
        float* base = outF + (size_t)zb*cZb + (size_t)zc*cZc;
        #pragma unroll
        for (int mt = 0; mt < 4; mt++) {
            int m = m0 + wm + mt*16 + ar;
            float* p0 = base + (size_t)m*ldcM;
            float* p1 = p0 + (size_t)8*ldcM;
            #pragma unroll
            for (int nt = 0; nt < 4; nt++) {
                int n = n0 + wn + nt*8 + ac;
                p0[(size_t)n*3]       = acc[mt][nt][0];
                p0[(size_t)(n+1)*3]   = acc[mt][nt][1];
                p1[(size_t)n*3]       = acc[mt][nt][2];
                p1[(size_t)(n+1)*3]   = acc[mt][nt][3];
            }
        }
    }
}

// -------------------- launcher --------------------
extern "C" void kernel_launch(void* const* d_in, const int* in_sizes, int n_in,
                              void* d_out, int out_size) {
    const float* ctx  = (const float*)d_in[0];
    const float* ques = (const float*)d_in[1];
    const float* wsim = (const float*)d_in[2];
    const float* W1s  = (const float*)d_in[3];
    const float* b1s  = (const float*)d_in[4];
    const float* W2s  = (const float*)d_in[5];
    const float* b2s  = (const float*)d_in[6];
    const float* W1e  = (const float*)d_in[7];
    const float* b1e  = (const float*)d_in[8];
    const float* W2e  = (const float*)d_in[9];
    const float* b2e  = (const float*)d_in[10];
    const float* Wb   = (const float*)d_in[11];
    float* out = (float*)d_out;

    float *q2, *rowmax, *q2c;
    __nv_bfloat16 *xs, *h1s, *s1s, *e1s, *Ts, *w1s, *w1e, *w2s, *w2e, *wbt;
    cudaGetSymbolAddress((void**)&q2, g_q2);
    cudaGetSymbolAddress((void**)&rowmax, g_rowmax);
    cudaGetSymbolAddress((void**)&q2c, g_q2c);
    cudaGetSymbolAddress((void**)&xs, g_xs);
    cudaGetSymbolAddress((void**)&h1s, g_h1s);
    cudaGetSymbolAddress((void**)&s1s, g_s1s);
    cudaGetSymbolAddress((void**)&e1s, g_e1s);
    cudaGetSymbolAddress((void**)&Ts, g_Ts);
    cudaGetSymbolAddress((void**)&w1s, g_w1s);
    cudaGetSymbolAddress((void**)&w1e, g_w1e);
    cudaGetSymbolAddress((void**)&w2s, g_w2s);
    cudaGetSymbolAddress((void**)&w2e, g_w2e);
    cudaGetSymbolAddress((void**)&wbt, g_wbt);

    // front-end
    qdot_kernel<<<dim3(Bz, LQ), 32>>>(ques, wsim, q2);
    sim_softmax_c2q_kernel<<<ROWS, 256>>>(ctx, ques, wsim, q2, xs, rowmax);
    bsoftmax_q2c_kernel<<<Bz, 256>>>(ctx, rowmax, q2c);
    fillx4_kernel<<<ROWS, 256>>>(ctx, q2c, xs);
    fill_const_kernel<<<ROWS, 64>>>(s1s, e1s);

    // weight prep (transpose + hi/lo split, B-layout hi,hi,lo)
    prep_bsplit<<<dim3(16, 32), dim3(32, 8)>>>(W1s, 512, w1s, 1024, 1024, 512);
    prep_bsplit<<<dim3(16, 32), dim3(32, 8)>>>(W1e, 512, w1e, 1024, 1024, 512);
    prep_bsplit<<<dim3(32, 16), dim3(32, 8)>>>(W2s, 1024, w2s, 512, 512, 1024);
    prep_bsplit<<<dim3(32, 16), dim3(32, 8)>>>(W2e, 1024, w2e, 512, 512, 1024);
    for (int c = 0; c < 3; c++)
        prep_bsplit<<<dim3(33, 34), dim3(32, 8)>>>(Wb + (size_t)c*1025, 3075,
                                                   wbt + (size_t)c*NB1*KS, 1025, KPAD_S, 1025);

    long long zero = 0;
    // FFW start: h1 = relu(x@W1s + b1s)
    mma_gemm<<<dim3(4, 64, 1), 256>>>(xs, KX, zero, zero, w1s, KX, zero, zero,
        512, 96, 1, 0, h1s, KH, 512, 1024, 1, b1s, 1, nullptr, 0, zero, zero);
    // s1 = h1@W2s + b2s  (A-layout hi,lo,hi)
    mma_gemm<<<dim3(8, 64, 1), 256>>>(h1s, KH, zero, zero, w2s, KH, zero, zero,
        1024, 48, 1, 0, s1s, KS, KPAD_S, 2*KPAD_S, 1, b2s, 0, nullptr, 0, zero, zero);
    // FFW end
    mma_gemm<<<dim3(4, 64, 1), 256>>>(xs, KX, zero, zero, w1e, KX, zero, zero,
        512, 96, 1, 0, h1s, KH, 512, 1024, 1, b1e, 1, nullptr, 0, zero, zero);
    // e1 = h1@W2e + b2e  (B-layout hi,hi,lo)
    mma_gemm<<<dim3(8, 64, 1), 256>>>(h1s, KH, zero, zero, w2e, KH, zero, zero,
        1024, 48, 1, 0, e1s, KS, KPAD_S, 2*KPAD_S, 0, b2e, 0, nullptr, 0, zero, zero);

    // Biaffine stage 1: T[z=b*3+c] = s1_b @ wbt_c^T  (A-layout out)
    mma_gemm<<<dim3(9, 4, 48), 256>>>(
        s1s, KS, (long long)LC*KS, zero,
        wbt, KS, zero, (long long)NB1*KS,
        1025, 102, 3,
        0, Ts, KS, KPAD_S, 2*KPAD_S, 1, nullptr, 0,
        nullptr, 0, (long long)3*LC*KS, (long long)LC*KS);

    // Biaffine stage 2: out[b,:,:,c] = T[z] @ e1_b^T  (float, col stride 3)
    mma_gemm<<<dim3(4, 4, 48), 256>>>(
        Ts, KS, (long long)3*LC*KS, (long long)LC*KS,
        e1s, KS, (long long)LC*KS, zero,
        512, 102, 3,
        1, nullptr, 0, 0, 0, 0, nullptr, 0,
        out, LC*3, (long long)LC*LC*3, 1ll);
}